// round 1
// baseline (speedup 1.0000x reference)
#include <cuda_runtime.h>
#include <cuda_bf16.h>
#include <math.h>

// Problem constants (fixed by the dataset)
#define Bz   128
#define Kz   128
#define Dz   512
#define Lz   2
#define DIz  1024
#define Mz   (Bz*Kz)        // 16384 rows
#define HWz  4096           // 64*64 attn map
#define POSz 64

typedef unsigned long long ull;

// ---------------- scratch (device globals; no allocations allowed) ----------
__device__ float g_x  [Mz*Dz];      // slots state
__device__ float g_lnf[Mz*Dz];      // LN output (fwd / ffn)
__device__ float g_lnb[Mz*Dz];      // LN output (bwd)
__device__ float g_h  [Mz*2*DIz];   // wide hidden (M x 2048)
__device__ float g_a  [Mz*DIz];     // GLU activations / enc buffer
__device__ float g_cat[Mz*2*Dz];    // concat(f, b)
__device__ float g_res[Mz*Dz];      // pre-norm residual
__device__ float g_cent[Mz*2];      // centroids

// ---------------- packed f32x2 helpers (sm_103a FFMA2 path) -----------------
__device__ __forceinline__ ull pack2(float x, float y){
  ull r; asm("mov.b64 %0, {%1, %2};" : "=l"(r) : "f"(x), "f"(y)); return r;
}
__device__ __forceinline__ void fma2(ull& d, ull a, ull b){
  asm("fma.rn.f32x2 %0, %1, %2, %0;" : "+l"(d) : "l"(a), "l"(b));
}
__device__ __forceinline__ float2 unpack2(ull v){
  float2 f; asm("mov.b64 {%0, %1}, %2;" : "=f"(f.x), "=f"(f.y) : "l"(v)); return f;
}

__device__ __forceinline__ float gelu_exact(float x){
  return 0.5f * x * (1.0f + erff(x * 0.70710678118654752f));
}
__device__ __forceinline__ float sigmoidf(float x){
  return 1.0f / (1.0f + expf(-x));
}

// ---------------- GEMM: Out = act(A @ W + bias) [+ Add] [* mask] ------------
// A: M x Kd (row-major, lda = Kd), W: Kd x N (row-major), all dims multiples of tile
#define BMt 128
#define BNt 64
#define BKt 16

template<int ACT, bool HAS_ADD, bool HAS_MASK>
__global__ __launch_bounds__(256) void gemm_kernel(
    const float* __restrict__ A, int Kd,
    const float* __restrict__ W, int N,
    const float* __restrict__ bias,
    const float* __restrict__ Add, int ldadd,
    const float* __restrict__ mask,
    float* __restrict__ Out, int ldout)
{
  __shared__ float As[BKt][BMt];
  __shared__ float Bs[BKt][BNt];
  const int tid = threadIdx.x;
  const int tx = tid & 15;     // 16 threads * 4 cols = 64 (N)
  const int ty = tid >> 4;     // 16 threads * 8 rows = 128 (M)
  const int m0 = blockIdx.y * BMt;
  const int n0 = blockIdx.x * BNt;

  ull acc[4][4];               // 4 m-pairs x 4 n, packed fp32x2 along M
#pragma unroll
  for (int i=0;i<4;i++)
#pragma unroll
    for (int j=0;j<4;j++) acc[i][j]=0ULL;

  const int ar0 = tid >> 2;            // rows 0..63
  const int ac0 = (tid & 3) << 2;      // k-cols 0,4,8,12
  const int ar1 = ar0 + 64;            // rows 64..127
  const int br  = tid >> 4;            // k-row 0..15
  const int bc  = (tid & 15) << 2;     // n-col group

  for (int k0 = 0; k0 < Kd; k0 += BKt) {
    float4 a0 = *(const float4*)&A[(size_t)(m0+ar0)*Kd + k0 + ac0];
    float4 a1 = *(const float4*)&A[(size_t)(m0+ar1)*Kd + k0 + ac0];
    float4 bv = *(const float4*)&W[(size_t)(k0+br)*N + n0 + bc];
    __syncthreads();
    As[ac0+0][ar0]=a0.x; As[ac0+1][ar0]=a0.y; As[ac0+2][ar0]=a0.z; As[ac0+3][ar0]=a0.w;
    As[ac0+0][ar1]=a1.x; As[ac0+1][ar1]=a1.y; As[ac0+2][ar1]=a1.z; As[ac0+3][ar1]=a1.w;
    *(float4*)&Bs[br][bc] = bv;
    __syncthreads();
#pragma unroll
    for (int k=0;k<BKt;k++){
      const ull* ap = (const ull*)&As[k][ty<<3];
      ull a_0=ap[0], a_1=ap[1], a_2=ap[2], a_3=ap[3];
      float4 b = *(const float4*)&Bs[k][tx<<2];
      ull bb0=pack2(b.x,b.x), bb1=pack2(b.y,b.y), bb2=pack2(b.z,b.z), bb3=pack2(b.w,b.w);
      fma2(acc[0][0],a_0,bb0); fma2(acc[0][1],a_0,bb1); fma2(acc[0][2],a_0,bb2); fma2(acc[0][3],a_0,bb3);
      fma2(acc[1][0],a_1,bb0); fma2(acc[1][1],a_1,bb1); fma2(acc[1][2],a_1,bb2); fma2(acc[1][3],a_1,bb3);
      fma2(acc[2][0],a_2,bb0); fma2(acc[2][1],a_2,bb1); fma2(acc[2][2],a_2,bb2); fma2(acc[2][3],a_2,bb3);
      fma2(acc[3][0],a_3,bb0); fma2(acc[3][1],a_3,bb1); fma2(acc[3][2],a_3,bb2); fma2(acc[3][3],a_3,bb3);
    }
  }

  float4 bi = *(const float4*)&bias[n0 + (tx<<2)];
  float bj[4] = {bi.x, bi.y, bi.z, bi.w};
#pragma unroll
  for (int i=0;i<4;i++){
    int m = m0 + (ty<<3) + (i<<1);
#pragma unroll
    for (int j=0;j<4;j++){
      int n = n0 + (tx<<2) + j;
      float2 c = unpack2(acc[i][j]);
      float v0 = c.x + bj[j];
      float v1 = c.y + bj[j];
      if (ACT==1){ v0 = gelu_exact(v0); v1 = gelu_exact(v1); }
      if (HAS_ADD){ v0 += Add[(size_t)m*ldadd + n]; v1 += Add[(size_t)(m+1)*ldadd + n]; }
      if (HAS_MASK){ v0 *= mask[m]; v1 *= mask[m+1]; }
      Out[(size_t)m*ldout + n]     = v0;
      Out[(size_t)(m+1)*ldout + n] = v1;
    }
  }
}

// ---------------- LayerNorm kernels (D = 512, 128 threads, float4/thread) ---
__device__ __forceinline__ float block_sum_128(float v, volatile float* sh){
#pragma unroll
  for (int o=16;o>0;o>>=1) v += __shfl_xor_sync(0xffffffffu, v, o);
  int w = threadIdx.x >> 5;
  if ((threadIdx.x & 31)==0) sh[w] = v;
  __syncthreads();
  float r = sh[0]+sh[1]+sh[2]+sh[3];
  __syncthreads();
  return r;
}

// Y1 = LN(X; g1,b1), optionally Y2 = LN(X; g2,b2)  (shared statistics)
__global__ __launch_bounds__(128) void ln_dual_kernel(
  const float* __restrict__ X,
  const float* __restrict__ g1, const float* __restrict__ b1, float* __restrict__ Y1,
  const float* __restrict__ g2, const float* __restrict__ b2, float* __restrict__ Y2)
{
  __shared__ float sh[4];
  int row = blockIdx.x, t = threadIdx.x;
  float4 v = ((const float4*)(X + (size_t)row*Dz))[t];
  float s = block_sum_128(v.x+v.y+v.z+v.w, sh);
  float mean = s * (1.0f/Dz);
  float dx=v.x-mean, dy=v.y-mean, dz=v.z-mean, dw=v.w-mean;
  float sq = block_sum_128(dx*dx+dy*dy+dz*dz+dw*dw, sh);
  float inv = rsqrtf(sq*(1.0f/Dz) + 1e-5f);
  {
    float4 G = ((const float4*)g1)[t]; float4 Bb = ((const float4*)b1)[t];
    float4 o = make_float4(dx*inv*G.x+Bb.x, dy*inv*G.y+Bb.y, dz*inv*G.z+Bb.z, dw*inv*G.w+Bb.w);
    ((float4*)(Y1 + (size_t)row*Dz))[t] = o;
  }
  if (Y2){
    float4 G = ((const float4*)g2)[t]; float4 Bb = ((const float4*)b2)[t];
    float4 o = make_float4(dx*inv*G.x+Bb.x, dy*inv*G.y+Bb.y, dz*inv*G.z+Bb.z, dw*inv*G.w+Bb.w);
    ((float4*)(Y2 + (size_t)row*Dz))[t] = o;
  }
}

// Y1 = LN(X; g1,b1);  Y2 = LN(Y1; g2,b2)   (chained, one pass)
__global__ __launch_bounds__(128) void ln_chain_kernel(
  const float* __restrict__ X,
  const float* __restrict__ g1, const float* __restrict__ b1, float* __restrict__ Y1,
  const float* __restrict__ g2, const float* __restrict__ b2, float* __restrict__ Y2)
{
  __shared__ float sh[4];
  int row = blockIdx.x, t = threadIdx.x;
  float4 v = ((const float4*)(X + (size_t)row*Dz))[t];
  float s = block_sum_128(v.x+v.y+v.z+v.w, sh);
  float mean = s * (1.0f/Dz);
  float dx=v.x-mean, dy=v.y-mean, dz=v.z-mean, dw=v.w-mean;
  float sq = block_sum_128(dx*dx+dy*dy+dz*dz+dw*dw, sh);
  float inv = rsqrtf(sq*(1.0f/Dz) + 1e-5f);
  float4 G1 = ((const float4*)g1)[t]; float4 B1 = ((const float4*)b1)[t];
  float4 y;
  y.x = dx*inv*G1.x+B1.x; y.y = dy*inv*G1.y+B1.y; y.z = dz*inv*G1.z+B1.z; y.w = dw*inv*G1.w+B1.w;
  ((float4*)(Y1 + (size_t)row*Dz))[t] = y;
  // second LN over y
  float s2 = block_sum_128(y.x+y.y+y.z+y.w, sh);
  float m2 = s2 * (1.0f/Dz);
  float ex=y.x-m2, ey=y.y-m2, ez=y.z-m2, ew=y.w-m2;
  float sq2 = block_sum_128(ex*ex+ey*ey+ez*ez+ew*ew, sh);
  float inv2 = rsqrtf(sq2*(1.0f/Dz) + 1e-5f);
  float4 G2 = ((const float4*)g2)[t]; float4 B2 = ((const float4*)b2)[t];
  float4 o = make_float4(ex*inv2*G2.x+B2.x, ey*inv2*G2.y+B2.y, ez*inv2*G2.z+B2.z, ew*inv2*G2.w+B2.w);
  ((float4*)(Y2 + (size_t)row*Dz))[t] = o;
}

// ---------------- centroids: (sum a*coord) / (sum a + 1e-8) -----------------
__global__ __launch_bounds__(256) void centroid_kernel(
  const float* __restrict__ attn, float* __restrict__ cent, float* __restrict__ cent_out)
{
  int bk = blockIdx.x;
  const float* a = attn + (size_t)bk*HWz;
  float s=0.f, sx=0.f, sy=0.f;
#pragma unroll 4
  for (int i=threadIdx.x; i<HWz; i+=256){
    float v = a[i];
    s  += v;
    sx += v * (float)(i & 63);
    sy += v * (float)(i >> 6);
  }
#pragma unroll
  for (int o=16;o>0;o>>=1){
    s  += __shfl_xor_sync(0xffffffffu, s,  o);
    sx += __shfl_xor_sync(0xffffffffu, sx, o);
    sy += __shfl_xor_sync(0xffffffffu, sy, o);
  }
  __shared__ float sh[24];
  int w = threadIdx.x >> 5;
  if ((threadIdx.x & 31)==0){ sh[w]=s; sh[8+w]=sx; sh[16+w]=sy; }
  __syncthreads();
  if (threadIdx.x==0){
    float S=0.f, SX=0.f, SY=0.f;
    for (int i=0;i<8;i++){ S+=sh[i]; SX+=sh[8+i]; SY+=sh[16+i]; }
    float invs = 1.0f/(S + 1e-8f);
    float cx = SX * (1.0f/63.0f) * invs;
    float cy = SY * (1.0f/63.0f) * invs;
    cent[bk*2]   = cx;
    cent[bk*2+1] = cy;
    if (cent_out){ cent_out[bk*2] = cx; cent_out[bk*2+1] = cy; }
  }
}

// ---------------- positional encoding rows (M x 256) ------------------------
__global__ __launch_bounds__(256) void enc_kernel(
  const float* __restrict__ cent, float* __restrict__ E)
{
  int row = blockIdx.x, j = threadIdx.x;   // j in [0,256)
  int f  = j >> 6;
  int jj = j & 63;
  int fi = jj & 31;
  float feat;
  if      (f==0) feat = cent[row*2];
  else if (f==1) feat = cent[row*2+1];
  else           feat = 0.1f;
  // freqs = 10000^(-fi/32) = exp(-fi * ln(10000)/32)
  float freq = expf(-(float)fi * 0.28782313662425575f);
  float ang = feat * freq * 3.14159f;
  E[(size_t)row*256 + j] = (jj < 32) ? sinf(ang) : cosf(ang);
}

// ---------------- GLU: silu(z) * sigmoid(gate) ------------------------------
__global__ __launch_bounds__(256) void glu_kernel(
  const float* __restrict__ Hh, float* __restrict__ Aout)
{
  int idx = blockIdx.x*256 + threadIdx.x;   // total = Mz*DIz
  int row = idx >> 10;
  int c   = idx & 1023;
  float z = Hh[(size_t)row*2048 + c];
  float g = Hh[(size_t)row*2048 + 1024 + c];
  Aout[idx] = z * sigmoidf(z) * sigmoidf(g);
}

// ---------------- host orchestration ----------------------------------------
extern "C" void kernel_launch(void* const* d_in, const int* in_sizes, int n_in,
                              void* d_out, int out_size)
{
  const float* slots     = (const float*)d_in[0];
  const float* keep      = (const float*)d_in[1];
  const float* attn      = (const float*)d_in[2];
  // d_in[3] = H, d_in[4] = W (compile-time known: 64x64)
  const float* pm1_w     = (const float*)d_in[5];
  const float* pm1_b     = (const float*)d_in[6];
  const float* pm2_w     = (const float*)d_in[7];
  const float* pm2_b     = (const float*)d_in[8];
  const float* fwd_ln_g  = (const float*)d_in[9];
  const float* fwd_ln_b  = (const float*)d_in[10];
  const float* fwd_in_w  = (const float*)d_in[11];
  const float* fwd_in_b  = (const float*)d_in[12];
  const float* fwd_out_w = (const float*)d_in[13];
  const float* fwd_out_b = (const float*)d_in[14];
  const float* bwd_ln_g  = (const float*)d_in[15];
  const float* bwd_ln_b  = (const float*)d_in[16];
  const float* bwd_in_w  = (const float*)d_in[17];
  const float* bwd_in_b  = (const float*)d_in[18];
  const float* bwd_out_w = (const float*)d_in[19];
  const float* bwd_out_b = (const float*)d_in[20];
  const float* merge_w   = (const float*)d_in[21];
  const float* merge_b   = (const float*)d_in[22];
  const float* norm_g    = (const float*)d_in[23];
  const float* norm_b    = (const float*)d_in[24];
  const float* ffn_ln_g  = (const float*)d_in[25];
  const float* ffn_ln_b  = (const float*)d_in[26];
  const float* ffn1_w    = (const float*)d_in[27];
  const float* ffn1_b    = (const float*)d_in[28];
  const float* ffn2_w    = (const float*)d_in[29];
  const float* ffn2_b    = (const float*)d_in[30];
  float* out = (float*)d_out;

  float *xg, *lnf, *lnb, *hh, *aa, *cat, *res, *cent;
  cudaGetSymbolAddress((void**)&xg,   g_x);
  cudaGetSymbolAddress((void**)&lnf,  g_lnf);
  cudaGetSymbolAddress((void**)&lnb,  g_lnb);
  cudaGetSymbolAddress((void**)&hh,   g_h);
  cudaGetSymbolAddress((void**)&aa,   g_a);
  cudaGetSymbolAddress((void**)&cat,  g_cat);
  cudaGetSymbolAddress((void**)&res,  g_res);
  cudaGetSymbolAddress((void**)&cent, g_cent);

  float* cent_out = nullptr;
  if ((long long)out_size >= (long long)Mz*Dz + (long long)Mz*2)
    cent_out = out + (size_t)Mz*Dz;

  const dim3 blk(256);
  const dim3 gN512 (Dz/BNt,      Mz/BMt);  // (8, 128)
  const dim3 gN2048(2048/BNt,    Mz/BMt);  // (32, 128)

  // centroids + positional encoding + slot update
  centroid_kernel<<<Mz, 256>>>(attn, cent, cent_out);
  enc_kernel<<<Mz, 256>>>(cent, aa);
  gemm_kernel<1,false,false><<<gN512, blk>>>(aa, 256, pm1_w, Dz, pm1_b,
                                             nullptr, 0, nullptr, lnf, Dz);
  gemm_kernel<0,true ,false><<<gN512, blk>>>(lnf, Dz, pm2_w, Dz, pm2_b,
                                             slots, Dz, nullptr, xg, Dz);

  for (int i = 0; i < Lz; i++) {
    const size_t oW_in  = (size_t)i * Dz * 2 * DIz;   // 512*2048
    const size_t oW_out = (size_t)i * DIz * Dz;       // 1024*512
    const size_t oW_mrg = (size_t)i * 2 * Dz * Dz;    // 1024*512
    const size_t oW_f1  = (size_t)i * Dz * 4 * Dz;    // 512*2048
    const size_t oW_f2  = (size_t)i * 4 * Dz * Dz;    // 2048*512

    // shared-input LN for fwd & bwd branches (ordering is a no-op — see analysis)
    ln_dual_kernel<<<Mz,128>>>(xg, fwd_ln_g+i*Dz, fwd_ln_b+i*Dz, lnf,
                                   bwd_ln_g+i*Dz, bwd_ln_b+i*Dz, lnb);
    // fwd branch
    gemm_kernel<0,false,false><<<gN2048, blk>>>(lnf, Dz, fwd_in_w+oW_in, 2*DIz,
                                                fwd_in_b+(size_t)i*2*DIz,
                                                nullptr, 0, nullptr, hh, 2*DIz);
    glu_kernel<<<(Mz*DIz)/256, blk>>>(hh, aa);
    gemm_kernel<0,true ,false><<<gN512, blk>>>(aa, DIz, fwd_out_w+oW_out, Dz,
                                               fwd_out_b+(size_t)i*Dz,
                                               xg, Dz, nullptr, cat, 2*Dz);
    // bwd branch
    gemm_kernel<0,false,false><<<gN2048, blk>>>(lnb, Dz, bwd_in_w+oW_in, 2*DIz,
                                                bwd_in_b+(size_t)i*2*DIz,
                                                nullptr, 0, nullptr, hh, 2*DIz);
    glu_kernel<<<(Mz*DIz)/256, blk>>>(hh, aa);
    gemm_kernel<0,true ,false><<<gN512, blk>>>(aa, DIz, bwd_out_w+oW_out, Dz,
                                               bwd_out_b+(size_t)i*Dz,
                                               xg, Dz, nullptr, cat+Dz, 2*Dz);
    // merge + residual, then chained LN (post-norm) and FFN input LN
    gemm_kernel<0,true ,false><<<gN512, blk>>>(cat, 2*Dz, merge_w+oW_mrg, Dz,
                                               merge_b+(size_t)i*Dz,
                                               xg, Dz, nullptr, res, Dz);
    ln_chain_kernel<<<Mz,128>>>(res, norm_g+i*Dz, norm_b+i*Dz, xg,
                                     ffn_ln_g+i*Dz, ffn_ln_b+i*Dz, lnf);
    // FFN
    gemm_kernel<1,false,false><<<gN2048, blk>>>(lnf, Dz, ffn1_w+oW_f1, 4*Dz,
                                                ffn1_b+(size_t)i*4*Dz,
                                                nullptr, 0, nullptr, hh, 4*Dz);
    float* dst = (i == Lz-1) ? out : xg;
    gemm_kernel<0,true ,true ><<<gN512, blk>>>(hh, 4*Dz, ffn2_w+oW_f2, Dz,
                                               ffn2_b+(size_t)i*Dz,
                                               xg, Dz, keep, dst, Dz);
  }
}

// round 3
// speedup vs baseline: 2.0052x; 2.0052x over previous
#include <cuda_runtime.h>
#include <cuda_bf16.h>
#include <math.h>
#include <cstdint>

// Problem constants (fixed by the dataset)
#define Bz   128
#define Kz   128
#define Dz   512
#define Lz   2
#define DIz  1024
#define Mz   (Bz*Kz)        // 16384 rows
#define HWz  4096           // 64*64 attn map

// GEMM tiling (Ampere-style mma.sync tf32)
#define BM 128
#define BN 128
#define BK 32
#define ASTR 36              // A smem row stride (floats), conflict-free frag loads
#define BSTR 136             // B smem row stride (floats)
#define A_TILE_F (BM*ASTR)   // 4608 floats
#define B_TILE_F (BK*BSTR)   // 4352 floats
#define STAGE_F  (A_TILE_F + B_TILE_F)          // 8960 floats
#define DSMEM_BYTES (2*STAGE_F*4)               // 71680 B

// ---------------- scratch (device globals; no allocations allowed) ----------
__device__ float g_x  [Mz*Dz];
__device__ float g_lnf[Mz*Dz];
__device__ float g_lnb[Mz*Dz];
__device__ float g_h  [Mz*2*DIz];
__device__ float g_a  [Mz*DIz];
__device__ float g_cat[Mz*2*Dz];
__device__ float g_res[Mz*Dz];
__device__ float g_cent[Mz*2];

// ---------------- helpers ---------------------------------------------------
__device__ __forceinline__ uint32_t smem_u32(const void* p){
  uint32_t a;
  asm("{ .reg .u64 t; cvta.to.shared.u64 t, %1; cvt.u32.u64 %0, t; }" : "=r"(a) : "l"(p));
  return a;
}
__device__ __forceinline__ void cpa16(void* dst, const void* src){
  asm volatile("cp.async.cg.shared.global [%0], [%1], 16;"
               :: "r"(smem_u32(dst)), "l"(src) : "memory");
}
__device__ __forceinline__ void cpa_commit(){
  asm volatile("cp.async.commit_group;" ::: "memory");
}
template<int N> __device__ __forceinline__ void cpa_wait(){
  asm volatile("cp.async.wait_group %0;" :: "n"(N) : "memory");
}
__device__ __forceinline__ void mma_tf32(float* d, const uint32_t* a, const uint32_t* b){
  asm volatile(
    "mma.sync.aligned.m16n8k8.row.col.f32.tf32.tf32.f32 "
    "{%0,%1,%2,%3}, {%4,%5,%6,%7}, {%8,%9}, {%0,%1,%2,%3};"
    : "+f"(d[0]), "+f"(d[1]), "+f"(d[2]), "+f"(d[3])
    : "r"(a[0]), "r"(a[1]), "r"(a[2]), "r"(a[3]), "r"(b[0]), "r"(b[1]));
}
__device__ __forceinline__ float gelu_exact(float x){
  return 0.5f * x * (1.0f + erff(x * 0.70710678118654752f));
}
__device__ __forceinline__ float sigmoidf(float x){
  return 1.0f / (1.0f + expf(-x));
}

// ---------------- tf32 mma.sync GEMM ----------------------------------------
// Out[M,N] = act(A[M,Kd] @ W[Kd,N] + bias) [+ Add] [* mask]
// Kd % 32 == 0, N % 128 == 0, M % 128 == 0
template<int ACT, bool HAS_ADD, bool HAS_MASK>
__global__ __launch_bounds__(256, 2) void gemm_mma(
    const float* __restrict__ A, int Kd,
    const float* __restrict__ W, int N,
    const float* __restrict__ bias,
    const float* __restrict__ Add, int ldadd,
    const float* __restrict__ mask,
    float* __restrict__ Out, int ldout)
{
  extern __shared__ float sm[];
  const int tid  = threadIdx.x;
  const int lane = tid & 31;
  const int warp = tid >> 5;
  const int wm   = warp & 1;          // 0..1 -> 64-row half
  const int wn   = warp >> 1;         // 0..3 -> 32-col quarter
  const int m0 = blockIdx.y * BM;
  const int n0 = blockIdx.x * BN;

  float acc[4][4][4];
#pragma unroll
  for (int i=0;i<4;i++)
#pragma unroll
    for (int j=0;j<4;j++)
#pragma unroll
      for (int r=0;r<4;r++) acc[i][j][r]=0.f;

  const float* Abase = A + (size_t)m0*Kd;
  const float* Wbase = W + n0;
  const int nch = Kd / BK;

  // ---- async tile loaders ----
  auto load_chunk = [&](int c, int buf){
    float* sA = sm + buf*STAGE_F;
    float* sB = sA + A_TILE_F;
    const float* Ab = Abase + c*BK;
    const float* Wb = Wbase + (size_t)c*BK*N;
#pragma unroll
    for (int i=0;i<4;i++){
      int idx = tid + i*256;
      int m  = idx >> 3;
      int k4 = idx & 7;
      cpa16(sA + m*ASTR + k4*4, Ab + (size_t)m*Kd + k4*4);
    }
#pragma unroll
    for (int i=0;i<4;i++){
      int idx = tid + i*256;
      int r  = idx >> 5;
      int c4 = idx & 31;
      cpa16(sB + r*BSTR + c4*4, Wb + (size_t)r*N + c4*4);
    }
    cpa_commit();
  };

  load_chunk(0, 0);

  for (int c = 0; c < nch; c++){
    const int buf = c & 1;
    if (c+1 < nch){ load_chunk(c+1, (c+1)&1); cpa_wait<1>(); }
    else          { cpa_wait<0>(); }
    __syncthreads();

    const float* sA = sm + buf*STAGE_F;
    const float* sB = sA + A_TILE_F;

#pragma unroll
    for (int ks = 0; ks < BK/8; ks++){
      uint32_t afr[4][4];
#pragma unroll
      for (int mi=0;mi<4;mi++){
        int r = wm*64 + mi*16 + (lane>>2);
        int cc = ks*8 + (lane&3);
        afr[mi][0] = __float_as_uint(sA[r*ASTR + cc]);
        afr[mi][1] = __float_as_uint(sA[(r+8)*ASTR + cc]);
        afr[mi][2] = __float_as_uint(sA[r*ASTR + cc + 4]);
        afr[mi][3] = __float_as_uint(sA[(r+8)*ASTR + cc + 4]);
      }
      uint32_t bfr[4][2];
#pragma unroll
      for (int nj=0;nj<4;nj++){
        int rr = ks*8 + (lane&3);
        int cc = wn*32 + nj*8 + (lane>>2);
        bfr[nj][0] = __float_as_uint(sB[rr*BSTR + cc]);
        bfr[nj][1] = __float_as_uint(sB[(rr+4)*BSTR + cc]);
      }
#pragma unroll
      for (int mi=0;mi<4;mi++)
#pragma unroll
        for (int nj=0;nj<4;nj++)
          mma_tf32(acc[mi][nj], afr[mi], bfr[nj]);
    }
    __syncthreads();
  }

  // ---- epilogue ----
#pragma unroll
  for (int mi=0;mi<4;mi++){
    const int r0 = m0 + wm*64 + mi*16 + (lane>>2);
    const int r1 = r0 + 8;
    const float mk0 = HAS_MASK ? mask[r0] : 1.f;
    const float mk1 = HAS_MASK ? mask[r1] : 1.f;
#pragma unroll
    for (int nj=0;nj<4;nj++){
      const int cb = n0 + wn*32 + nj*8 + (lane&3)*2;
      const float b0 = bias[cb], b1 = bias[cb+1];
      float v00 = acc[mi][nj][0] + b0;
      float v01 = acc[mi][nj][1] + b1;
      float v10 = acc[mi][nj][2] + b0;
      float v11 = acc[mi][nj][3] + b1;
      if (ACT == 1){
        v00 = gelu_exact(v00); v01 = gelu_exact(v01);
        v10 = gelu_exact(v10); v11 = gelu_exact(v11);
      }
      if (HAS_ADD){
        v00 += Add[(size_t)r0*ldadd + cb];   v01 += Add[(size_t)r0*ldadd + cb+1];
        v10 += Add[(size_t)r1*ldadd + cb];   v11 += Add[(size_t)r1*ldadd + cb+1];
      }
      if (HAS_MASK){ v00*=mk0; v01*=mk0; v10*=mk1; v11*=mk1; }
      *(float2*)&Out[(size_t)r0*ldout + cb] = make_float2(v00, v01);
      *(float2*)&Out[(size_t)r1*ldout + cb] = make_float2(v10, v11);
    }
  }
}

// ---------------- LayerNorm kernels (D = 512) -------------------------------
__device__ __forceinline__ float block_sum_128(float v, volatile float* sh){
#pragma unroll
  for (int o=16;o>0;o>>=1) v += __shfl_xor_sync(0xffffffffu, v, o);
  int w = threadIdx.x >> 5;
  if ((threadIdx.x & 31)==0) sh[w] = v;
  __syncthreads();
  float r = sh[0]+sh[1]+sh[2]+sh[3];
  __syncthreads();
  return r;
}

__global__ __launch_bounds__(128) void ln_dual_kernel(
  const float* __restrict__ X,
  const float* __restrict__ g1, const float* __restrict__ b1, float* __restrict__ Y1,
  const float* __restrict__ g2, const float* __restrict__ b2, float* __restrict__ Y2)
{
  __shared__ float sh[4];
  int row = blockIdx.x, t = threadIdx.x;
  float4 v = ((const float4*)(X + (size_t)row*Dz))[t];
  float s = block_sum_128(v.x+v.y+v.z+v.w, sh);
  float mean = s * (1.0f/Dz);
  float dx=v.x-mean, dy=v.y-mean, dz=v.z-mean, dw=v.w-mean;
  float sq = block_sum_128(dx*dx+dy*dy+dz*dz+dw*dw, sh);
  float inv = rsqrtf(sq*(1.0f/Dz) + 1e-5f);
  {
    float4 G = ((const float4*)g1)[t]; float4 Bb = ((const float4*)b1)[t];
    float4 o = make_float4(dx*inv*G.x+Bb.x, dy*inv*G.y+Bb.y, dz*inv*G.z+Bb.z, dw*inv*G.w+Bb.w);
    ((float4*)(Y1 + (size_t)row*Dz))[t] = o;
  }
  if (Y2){
    float4 G = ((const float4*)g2)[t]; float4 Bb = ((const float4*)b2)[t];
    float4 o = make_float4(dx*inv*G.x+Bb.x, dy*inv*G.y+Bb.y, dz*inv*G.z+Bb.z, dw*inv*G.w+Bb.w);
    ((float4*)(Y2 + (size_t)row*Dz))[t] = o;
  }
}

__global__ __launch_bounds__(128) void ln_chain_kernel(
  const float* __restrict__ X,
  const float* __restrict__ g1, const float* __restrict__ b1, float* __restrict__ Y1,
  const float* __restrict__ g2, const float* __restrict__ b2, float* __restrict__ Y2)
{
  __shared__ float sh[4];
  int row = blockIdx.x, t = threadIdx.x;
  float4 v = ((const float4*)(X + (size_t)row*Dz))[t];
  float s = block_sum_128(v.x+v.y+v.z+v.w, sh);
  float mean = s * (1.0f/Dz);
  float dx=v.x-mean, dy=v.y-mean, dz=v.z-mean, dw=v.w-mean;
  float sq = block_sum_128(dx*dx+dy*dy+dz*dz+dw*dw, sh);
  float inv = rsqrtf(sq*(1.0f/Dz) + 1e-5f);
  float4 G1 = ((const float4*)g1)[t]; float4 B1 = ((const float4*)b1)[t];
  float4 y;
  y.x = dx*inv*G1.x+B1.x; y.y = dy*inv*G1.y+B1.y; y.z = dz*inv*G1.z+B1.z; y.w = dw*inv*G1.w+B1.w;
  ((float4*)(Y1 + (size_t)row*Dz))[t] = y;
  float s2 = block_sum_128(y.x+y.y+y.z+y.w, sh);
  float m2 = s2 * (1.0f/Dz);
  float ex=y.x-m2, ey=y.y-m2, ez=y.z-m2, ew=y.w-m2;
  float sq2 = block_sum_128(ex*ex+ey*ey+ez*ez+ew*ew, sh);
  float inv2 = rsqrtf(sq2*(1.0f/Dz) + 1e-5f);
  float4 G2 = ((const float4*)g2)[t]; float4 B2 = ((const float4*)b2)[t];
  float4 o = make_float4(ex*inv2*G2.x+B2.x, ey*inv2*G2.y+B2.y, ez*inv2*G2.z+B2.z, ew*inv2*G2.w+B2.w);
  ((float4*)(Y2 + (size_t)row*Dz))[t] = o;
}

// ---------------- centroids -------------------------------------------------
__global__ __launch_bounds__(256) void centroid_kernel(
  const float* __restrict__ attn, float* __restrict__ cent, float* __restrict__ cent_out)
{
  int bk = blockIdx.x;
  const float* a = attn + (size_t)bk*HWz;
  float s=0.f, sx=0.f, sy=0.f;
#pragma unroll 4
  for (int i=threadIdx.x; i<HWz; i+=256){
    float v = a[i];
    s  += v;
    sx += v * (float)(i & 63);
    sy += v * (float)(i >> 6);
  }
#pragma unroll
  for (int o=16;o>0;o>>=1){
    s  += __shfl_xor_sync(0xffffffffu, s,  o);
    sx += __shfl_xor_sync(0xffffffffu, sx, o);
    sy += __shfl_xor_sync(0xffffffffu, sy, o);
  }
  __shared__ float sh[24];
  int w = threadIdx.x >> 5;
  if ((threadIdx.x & 31)==0){ sh[w]=s; sh[8+w]=sx; sh[16+w]=sy; }
  __syncthreads();
  if (threadIdx.x==0){
    float S=0.f, SX=0.f, SY=0.f;
    for (int i=0;i<8;i++){ S+=sh[i]; SX+=sh[8+i]; SY+=sh[16+i]; }
    float invs = 1.0f/(S + 1e-8f);
    float cx = SX * (1.0f/63.0f) * invs;
    float cy = SY * (1.0f/63.0f) * invs;
    cent[bk*2]   = cx;
    cent[bk*2+1] = cy;
    if (cent_out){ cent_out[bk*2] = cx; cent_out[bk*2+1] = cy; }
  }
}

// ---------------- positional encoding rows (M x 256) ------------------------
__global__ __launch_bounds__(256) void enc_kernel(
  const float* __restrict__ cent, float* __restrict__ E)
{
  int row = blockIdx.x, j = threadIdx.x;
  int f  = j >> 6;
  int jj = j & 63;
  int fi = jj & 31;
  float feat;
  if      (f==0) feat = cent[row*2];
  else if (f==1) feat = cent[row*2+1];
  else           feat = 0.1f;
  float freq = expf(-(float)fi * 0.28782313662425575f);
  float ang = feat * freq * 3.14159f;
  E[(size_t)row*256 + j] = (jj < 32) ? sinf(ang) : cosf(ang);
}

// ---------------- GLU -------------------------------------------------------
__global__ __launch_bounds__(256) void glu_kernel(
  const float* __restrict__ Hh, float* __restrict__ Aout)
{
  int idx = blockIdx.x*256 + threadIdx.x;
  int row = idx >> 10;
  int c   = idx & 1023;
  float z = Hh[(size_t)row*2048 + c];
  float g = Hh[(size_t)row*2048 + 1024 + c];
  Aout[idx] = z * sigmoidf(z) * sigmoidf(g);
}

// ---------------- host orchestration ----------------------------------------
extern "C" void kernel_launch(void* const* d_in, const int* in_sizes, int n_in,
                              void* d_out, int out_size)
{
  const float* slots     = (const float*)d_in[0];
  const float* keep      = (const float*)d_in[1];
  const float* attn      = (const float*)d_in[2];
  const float* pm1_w     = (const float*)d_in[5];
  const float* pm1_b     = (const float*)d_in[6];
  const float* pm2_w     = (const float*)d_in[7];
  const float* pm2_b     = (const float*)d_in[8];
  const float* fwd_ln_g  = (const float*)d_in[9];
  const float* fwd_ln_b  = (const float*)d_in[10];
  const float* fwd_in_w  = (const float*)d_in[11];
  const float* fwd_in_b  = (const float*)d_in[12];
  const float* fwd_out_w = (const float*)d_in[13];
  const float* fwd_out_b = (const float*)d_in[14];
  const float* bwd_ln_g  = (const float*)d_in[15];
  const float* bwd_ln_b  = (const float*)d_in[16];
  const float* bwd_in_w  = (const float*)d_in[17];
  const float* bwd_in_b  = (const float*)d_in[18];
  const float* bwd_out_w = (const float*)d_in[19];
  const float* bwd_out_b = (const float*)d_in[20];
  const float* merge_w   = (const float*)d_in[21];
  const float* merge_b   = (const float*)d_in[22];
  const float* norm_g    = (const float*)d_in[23];
  const float* norm_b    = (const float*)d_in[24];
  const float* ffn_ln_g  = (const float*)d_in[25];
  const float* ffn_ln_b  = (const float*)d_in[26];
  const float* ffn1_w    = (const float*)d_in[27];
  const float* ffn1_b    = (const float*)d_in[28];
  const float* ffn2_w    = (const float*)d_in[29];
  const float* ffn2_b    = (const float*)d_in[30];
  float* out = (float*)d_out;

  float *xg, *lnf, *lnb, *hh, *aa, *cat, *res, *cent;
  cudaGetSymbolAddress((void**)&xg,   g_x);
  cudaGetSymbolAddress((void**)&lnf,  g_lnf);
  cudaGetSymbolAddress((void**)&lnb,  g_lnb);
  cudaGetSymbolAddress((void**)&hh,   g_h);
  cudaGetSymbolAddress((void**)&aa,   g_a);
  cudaGetSymbolAddress((void**)&cat,  g_cat);
  cudaGetSymbolAddress((void**)&res,  g_res);
  cudaGetSymbolAddress((void**)&cent, g_cent);

  float* cent_out = nullptr;
  if ((long long)out_size >= (long long)Mz*Dz + (long long)Mz*2)
    cent_out = out + (size_t)Mz*Dz;

  cudaFuncSetAttribute(gemm_mma<1,false,false>, cudaFuncAttributeMaxDynamicSharedMemorySize, DSMEM_BYTES);
  cudaFuncSetAttribute(gemm_mma<0,false,false>, cudaFuncAttributeMaxDynamicSharedMemorySize, DSMEM_BYTES);
  cudaFuncSetAttribute(gemm_mma<0,true ,false>, cudaFuncAttributeMaxDynamicSharedMemorySize, DSMEM_BYTES);
  cudaFuncSetAttribute(gemm_mma<0,true ,true >, cudaFuncAttributeMaxDynamicSharedMemorySize, DSMEM_BYTES);

  const dim3 blk(256);
  const dim3 gN512 (Dz/BN,   Mz/BM);   // (4, 128)
  const dim3 gN2048(2048/BN, Mz/BM);   // (16, 128)

  // centroids + positional encoding + slot update
  centroid_kernel<<<Mz, 256>>>(attn, cent, cent_out);
  enc_kernel<<<Mz, 256>>>(cent, aa);
  gemm_mma<1,false,false><<<gN512, blk, DSMEM_BYTES>>>(aa, 256, pm1_w, Dz, pm1_b,
                                                       nullptr, 0, nullptr, lnf, Dz);
  gemm_mma<0,true ,false><<<gN512, blk, DSMEM_BYTES>>>(lnf, Dz, pm2_w, Dz, pm2_b,
                                                       slots, Dz, nullptr, xg, Dz);

  for (int i = 0; i < Lz; i++) {
    const size_t oW_in  = (size_t)i * Dz * 2 * DIz;
    const size_t oW_out = (size_t)i * DIz * Dz;
    const size_t oW_mrg = (size_t)i * 2 * Dz * Dz;
    const size_t oW_f1  = (size_t)i * Dz * 4 * Dz;
    const size_t oW_f2  = (size_t)i * 4 * Dz * Dz;

    ln_dual_kernel<<<Mz,128>>>(xg, fwd_ln_g+i*Dz, fwd_ln_b+i*Dz, lnf,
                                   bwd_ln_g+i*Dz, bwd_ln_b+i*Dz, lnb);
    // fwd branch
    gemm_mma<0,false,false><<<gN2048, blk, DSMEM_BYTES>>>(lnf, Dz, fwd_in_w+oW_in, 2*DIz,
                                                fwd_in_b+(size_t)i*2*DIz,
                                                nullptr, 0, nullptr, hh, 2*DIz);
    glu_kernel<<<(Mz*DIz)/256, blk>>>(hh, aa);
    gemm_mma<0,true ,false><<<gN512, blk, DSMEM_BYTES>>>(aa, DIz, fwd_out_w+oW_out, Dz,
                                               fwd_out_b+(size_t)i*Dz,
                                               xg, Dz, nullptr, cat, 2*Dz);
    // bwd branch
    gemm_mma<0,false,false><<<gN2048, blk, DSMEM_BYTES>>>(lnb, Dz, bwd_in_w+oW_in, 2*DIz,
                                                bwd_in_b+(size_t)i*2*DIz,
                                                nullptr, 0, nullptr, hh, 2*DIz);
    glu_kernel<<<(Mz*DIz)/256, blk>>>(hh, aa);
    gemm_mma<0,true ,false><<<gN512, blk, DSMEM_BYTES>>>(aa, DIz, bwd_out_w+oW_out, Dz,
                                               bwd_out_b+(size_t)i*Dz,
                                               xg, Dz, nullptr, cat+Dz, 2*Dz);
    // merge + residual, then chained LN
    gemm_mma<0,true ,false><<<gN512, blk, DSMEM_BYTES>>>(cat, 2*Dz, merge_w+oW_mrg, Dz,
                                               merge_b+(size_t)i*Dz,
                                               xg, Dz, nullptr, res, Dz);
    ln_chain_kernel<<<Mz,128>>>(res, norm_g+i*Dz, norm_b+i*Dz, xg,
                                     ffn_ln_g+i*Dz, ffn_ln_b+i*Dz, lnf);
    // FFN
    gemm_mma<1,false,false><<<gN2048, blk, DSMEM_BYTES>>>(lnf, Dz, ffn1_w+oW_f1, 4*Dz,
                                                ffn1_b+(size_t)i*4*Dz,
                                                nullptr, 0, nullptr, hh, 4*Dz);
    float* dst = (i == Lz-1) ? out : xg;
    gemm_mma<0,true ,true ><<<gN512, blk, DSMEM_BYTES>>>(hh, 4*Dz, ffn2_w+oW_f2, Dz,
                                               ffn2_b+(size_t)i*Dz,
                                               xg, Dz, keep, dst, Dz);
  }
}

// round 4
// speedup vs baseline: 3.1984x; 1.5950x over previous
#include <cuda_runtime.h>
#include <cuda_bf16.h>
#include <math.h>
#include <cstdint>

// Problem constants
#define Bz   128
#define Kz   128
#define Dz   512
#define Lz   2
#define DIz  1024
#define Mz   (Bz*Kz)        // 16384 rows
#define HWz  4096

// GEMM tiling: CTA 128 threads, tile 128x128, 4 warps of 64x64, BK=32
#define BM 128
#define BN 128
#define BK 32
#define ASTR 36
#define BSTR 136
#define A_TILE_F (BM*ASTR)                      // 4608
#define B_TILE_F (BK*BSTR)                      // 4352
#define STAGE_F  (A_TILE_F + B_TILE_F)          // 8960
#define DSMEM_BYTES (2*STAGE_F*4)               // 71680 B

// ---------------- scratch globals -------------------------------------------
__device__ float g_x   [Mz*Dz];
__device__ float g_lnf [Mz*Dz];
__device__ float g_h   [Mz*2048];       // GLU out / ffn1 out
__device__ float g_res [Mz*Dz];
__device__ float g_enc [Mz*256];
__device__ float g_cent[Mz*2];
// precomputed weights/biases
__device__ float g_wcat[2*512*4096];    // folded+permuted in-proj (z/gate interleaved)
__device__ float g_bcat[2*4096];
__device__ float g_wmid[2*2560*512];    // [WfoMt ; WboMb ; Mt+Mb]
__device__ float g_bmid[2*512];
__device__ float g_wf1 [2*512*2048];    // folded ffn1
__device__ float g_bf1 [2*2048];
__device__ float g_zero[512];           // zero-init bias

// ---------------- helpers ---------------------------------------------------
__device__ __forceinline__ uint32_t smem_u32(const void* p){
  uint32_t a;
  asm("{ .reg .u64 t; cvta.to.shared.u64 t, %1; cvt.u32.u64 %0, t; }" : "=r"(a) : "l"(p));
  return a;
}
__device__ __forceinline__ void cpa16(void* dst, const void* src){
  asm volatile("cp.async.cg.shared.global [%0], [%1], 16;"
               :: "r"(smem_u32(dst)), "l"(src) : "memory");
}
__device__ __forceinline__ void cpa_commit(){
  asm volatile("cp.async.commit_group;" ::: "memory");
}
template<int N> __device__ __forceinline__ void cpa_wait(){
  asm volatile("cp.async.wait_group %0;" :: "n"(N) : "memory");
}
__device__ __forceinline__ void mma_tf32(float* d, const uint32_t* a, const uint32_t* b){
  asm volatile(
    "mma.sync.aligned.m16n8k8.row.col.f32.tf32.tf32.f32 "
    "{%0,%1,%2,%3}, {%4,%5,%6,%7}, {%8,%9}, {%0,%1,%2,%3};"
    : "+f"(d[0]), "+f"(d[1]), "+f"(d[2]), "+f"(d[3])
    : "r"(a[0]), "r"(a[1]), "r"(a[2]), "r"(a[3]), "r"(b[0]), "r"(b[1]));
}
__device__ __forceinline__ float tf32rna(float x){
  float r; asm("cvt.rna.tf32.f32 %0, %1;" : "=f"(r) : "f"(x)); return r;
}
__device__ __forceinline__ float gelu_exact(float x){
  return 0.5f * x * (1.0f + erff(x * 0.70710678118654752f));
}
__device__ __forceinline__ float sigmoidf(float x){
  return 1.0f / (1.0f + expf(-x));
}

// ---------------- tf32 mma GEMM: Out = act(Acat @ W + bias) [+Add][*mask] ----
// Acat = [A1 (K1 cols) | A2 (Ktot-K1 cols)], row-major with strides ld1/ld2.
// ACT: 0 none, 1 gelu, 2 GLU (pairs of output cols -> silu(even)*sigmoid(odd),
//      written to col ((n&2047)>>1) + (n>>11)*1024, ldout applies)
template<int ACT, bool HAS_ADD, bool HAS_MASK>
__global__ __launch_bounds__(128, 2) void gemm2(
    const float* __restrict__ A1, int ld1, int K1,
    const float* __restrict__ A2, int ld2, int Ktot,
    const float* __restrict__ W, int N,
    const float* __restrict__ bias,
    const float* __restrict__ Add, int ldadd,
    const float* __restrict__ mask,
    float* __restrict__ Out, int ldout)
{
  extern __shared__ float sm[];
  const int tid  = threadIdx.x;
  const int lane = tid & 31;
  const int warp = tid >> 5;
  const int wm   = warp & 1;          // row half (64)
  const int wn   = warp >> 1;         // col half (64)
  const int m0 = blockIdx.y * BM;
  const int n0 = blockIdx.x * BN;

  float acc[4][8][4];
#pragma unroll
  for (int i=0;i<4;i++)
#pragma unroll
    for (int j=0;j<8;j++)
#pragma unroll
      for (int r=0;r<4;r++) acc[i][j][r]=0.f;

  const int nch = Ktot / BK;

  auto load_chunk = [&](int c, int buf){
    const int k0 = c*BK;
    const float* src; int ld;
    if (k0 < K1){ src = A1 + (size_t)m0*ld1 + k0; ld = ld1; }
    else        { src = A2 + (size_t)m0*ld2 + (k0 - K1); ld = ld2; }
    float* sA = sm + buf*STAGE_F;
    float* sB = sA + A_TILE_F;
    const float* Wb = W + (size_t)k0*N + n0;
#pragma unroll
    for (int i=0;i<8;i++){
      int idx = tid + i*128;
      int m  = idx >> 3;
      int k4 = idx & 7;
      cpa16(sA + m*ASTR + k4*4, src + (size_t)m*ld + k4*4);
    }
#pragma unroll
    for (int i=0;i<8;i++){
      int idx = tid + i*128;
      int r  = idx >> 5;
      int c4 = idx & 31;
      cpa16(sB + r*BSTR + c4*4, Wb + (size_t)r*N + c4*4);
    }
    cpa_commit();
  };

  load_chunk(0, 0);

  for (int c = 0; c < nch; c++){
    const int buf = c & 1;
    if (c+1 < nch){ load_chunk(c+1, (c+1)&1); cpa_wait<1>(); }
    else          { cpa_wait<0>(); }
    __syncthreads();

    const float* sA = sm + buf*STAGE_F;
    const float* sB = sA + A_TILE_F;

#pragma unroll
    for (int ks = 0; ks < BK/8; ks++){
      uint32_t afr[4][4];
#pragma unroll
      for (int mi=0;mi<4;mi++){
        int r  = wm*64 + mi*16 + (lane>>2);
        int cc = ks*8 + (lane&3);
        afr[mi][0] = __float_as_uint(sA[r*ASTR + cc]);
        afr[mi][1] = __float_as_uint(sA[(r+8)*ASTR + cc]);
        afr[mi][2] = __float_as_uint(sA[r*ASTR + cc + 4]);
        afr[mi][3] = __float_as_uint(sA[(r+8)*ASTR + cc + 4]);
      }
      uint32_t bfr[8][2];
#pragma unroll
      for (int nj=0;nj<8;nj++){
        int rr = ks*8 + (lane&3);
        int cc = wn*64 + nj*8 + (lane>>2);
        bfr[nj][0] = __float_as_uint(sB[rr*BSTR + cc]);
        bfr[nj][1] = __float_as_uint(sB[(rr+4)*BSTR + cc]);
      }
#pragma unroll
      for (int mi=0;mi<4;mi++)
#pragma unroll
        for (int nj=0;nj<8;nj++)
          mma_tf32(acc[mi][nj], afr[mi], bfr[nj]);
    }
    __syncthreads();
  }

  // ---- epilogue ----
#pragma unroll
  for (int mi=0;mi<4;mi++){
    const int r0 = m0 + wm*64 + mi*16 + (lane>>2);
    const int r1 = r0 + 8;
    const float mk0 = HAS_MASK ? mask[r0] : 1.f;
    const float mk1 = HAS_MASK ? mask[r1] : 1.f;
#pragma unroll
    for (int nj=0;nj<8;nj++){
      const int cb = n0 + wn*64 + nj*8 + (lane&3)*2;
      const float b0 = bias[cb], b1 = bias[cb+1];
      float v0 = acc[mi][nj][0] + b0;
      float v1 = acc[mi][nj][1] + b1;
      float v2 = acc[mi][nj][2] + b0;
      float v3 = acc[mi][nj][3] + b1;
      if (ACT == 2){
        // GLU: even col = z, odd col = gate
        const int oc = ((cb & 2047) >> 1) + (cb >> 11)*1024;
        Out[(size_t)r0*ldout + oc] = v0 * sigmoidf(v0) * sigmoidf(v1);
        Out[(size_t)r1*ldout + oc] = v2 * sigmoidf(v2) * sigmoidf(v3);
      } else {
        if (ACT == 1){
          v0 = gelu_exact(v0); v1 = gelu_exact(v1);
          v2 = gelu_exact(v2); v3 = gelu_exact(v3);
        }
        if (HAS_ADD){
          v0 += Add[(size_t)r0*ldadd + cb];   v1 += Add[(size_t)r0*ldadd + cb+1];
          v2 += Add[(size_t)r1*ldadd + cb];   v3 += Add[(size_t)r1*ldadd + cb+1];
        }
        if (HAS_MASK){ v0*=mk0; v1*=mk0; v2*=mk1; v3*=mk1; }
        *(float2*)&Out[(size_t)r0*ldout + cb] = make_float2(v0, v1);
        *(float2*)&Out[(size_t)r1*ldout + cb] = make_float2(v2, v3);
      }
    }
  }
}

// ---------------- LayerNorm kernels (D=512) ---------------------------------
__device__ __forceinline__ float block_sum_128(float v, volatile float* sh){
#pragma unroll
  for (int o=16;o>0;o>>=1) v += __shfl_xor_sync(0xffffffffu, v, o);
  int w = threadIdx.x >> 5;
  if ((threadIdx.x & 31)==0) sh[w] = v;
  __syncthreads();
  float r = sh[0]+sh[1]+sh[2]+sh[3];
  __syncthreads();
  return r;
}

// Y = normalize(X) (no affine)
__global__ __launch_bounds__(128) void ln_plain_kernel(
  const float* __restrict__ X, float* __restrict__ Y)
{
  __shared__ float sh[4];
  int row = blockIdx.x, t = threadIdx.x;
  float4 v = ((const float4*)(X + (size_t)row*Dz))[t];
  float s = block_sum_128(v.x+v.y+v.z+v.w, sh);
  float mean = s * (1.0f/Dz);
  float dx=v.x-mean, dy=v.y-mean, dz=v.z-mean, dw=v.w-mean;
  float sq = block_sum_128(dx*dx+dy*dy+dz*dz+dw*dw, sh);
  float inv = rsqrtf(sq*(1.0f/Dz) + 1e-5f);
  ((float4*)(Y + (size_t)row*Dz))[t] = make_float4(dx*inv, dy*inv, dz*inv, dw*inv);
}

// Y1 = LN(X; g, b);  Y2 = normalize(Y1)
__global__ __launch_bounds__(128) void ln_chain2_kernel(
  const float* __restrict__ X,
  const float* __restrict__ g, const float* __restrict__ b,
  float* __restrict__ Y1, float* __restrict__ Y2)
{
  __shared__ float sh[4];
  int row = blockIdx.x, t = threadIdx.x;
  float4 v = ((const float4*)(X + (size_t)row*Dz))[t];
  float s = block_sum_128(v.x+v.y+v.z+v.w, sh);
  float mean = s * (1.0f/Dz);
  float dx=v.x-mean, dy=v.y-mean, dz=v.z-mean, dw=v.w-mean;
  float sq = block_sum_128(dx*dx+dy*dy+dz*dz+dw*dw, sh);
  float inv = rsqrtf(sq*(1.0f/Dz) + 1e-5f);
  float4 G = ((const float4*)g)[t]; float4 Bb = ((const float4*)b)[t];
  float4 y = make_float4(dx*inv*G.x+Bb.x, dy*inv*G.y+Bb.y, dz*inv*G.z+Bb.z, dw*inv*G.w+Bb.w);
  ((float4*)(Y1 + (size_t)row*Dz))[t] = y;
  float s2 = block_sum_128(y.x+y.y+y.z+y.w, sh);
  float m2 = s2 * (1.0f/Dz);
  float ex=y.x-m2, ey=y.y-m2, ez=y.z-m2, ew=y.w-m2;
  float sq2 = block_sum_128(ex*ex+ey*ey+ez*ez+ew*ew, sh);
  float inv2 = rsqrtf(sq2*(1.0f/Dz) + 1e-5f);
  ((float4*)(Y2 + (size_t)row*Dz))[t] = make_float4(ex*inv2, ey*inv2, ez*inv2, ew*inv2);
}

// ---------------- centroids / enc -------------------------------------------
__global__ __launch_bounds__(256) void centroid_kernel(
  const float* __restrict__ attn, float* __restrict__ cent, float* __restrict__ cent_out)
{
  int bk = blockIdx.x;
  const float* a = attn + (size_t)bk*HWz;
  float s=0.f, sx=0.f, sy=0.f;
#pragma unroll 4
  for (int i=threadIdx.x; i<HWz; i+=256){
    float v = a[i];
    s  += v;
    sx += v * (float)(i & 63);
    sy += v * (float)(i >> 6);
  }
#pragma unroll
  for (int o=16;o>0;o>>=1){
    s  += __shfl_xor_sync(0xffffffffu, s,  o);
    sx += __shfl_xor_sync(0xffffffffu, sx, o);
    sy += __shfl_xor_sync(0xffffffffu, sy, o);
  }
  __shared__ float sh[24];
  int w = threadIdx.x >> 5;
  if ((threadIdx.x & 31)==0){ sh[w]=s; sh[8+w]=sx; sh[16+w]=sy; }
  __syncthreads();
  if (threadIdx.x==0){
    float S=0.f, SX=0.f, SY=0.f;
    for (int i=0;i<8;i++){ S+=sh[i]; SX+=sh[8+i]; SY+=sh[16+i]; }
    float invs = 1.0f/(S + 1e-8f);
    float cx = SX * (1.0f/63.0f) * invs;
    float cy = SY * (1.0f/63.0f) * invs;
    cent[bk*2]   = cx;
    cent[bk*2+1] = cy;
    if (cent_out){ cent_out[bk*2] = cx; cent_out[bk*2+1] = cy; }
  }
}

__global__ __launch_bounds__(256) void enc_kernel(
  const float* __restrict__ cent, float* __restrict__ E)
{
  int row = blockIdx.x, j = threadIdx.x;
  int f  = j >> 6;
  int jj = j & 63;
  int fi = jj & 31;
  float feat;
  if      (f==0) feat = cent[row*2];
  else if (f==1) feat = cent[row*2+1];
  else           feat = 0.1f;
  float freq = expf(-(float)fi * 0.28782313662425575f);
  float ang = feat * freq * 3.14159f;
  E[(size_t)row*256 + j] = (jj < 32) ? sinf(ang) : cosf(ang);
}

// ---------------- weight precompute kernels ---------------------------------
// Wcat[i][k][n]: z/gate interleaved, LN-gamma folded, tf32-rounded
__global__ __launch_bounds__(256) void build_wcat(
  const float* __restrict__ fw, const float* __restrict__ bw,
  const float* __restrict__ fg, const float* __restrict__ bg)
{
  size_t idx = (size_t)blockIdx.x*256 + threadIdx.x;   // 2*512*4096
  int n = idx & 4095;
  int k = (idx >> 12) & 511;
  int i = (int)(idx >> 21);
  int br = n >> 11;
  int j2 = n & 2047;
  int src = (j2 & 1) ? 1024 + (j2 >> 1) : (j2 >> 1);
  const float* W = (br ? bw : fw) + (size_t)i*512*2048;
  const float* G = (br ? bg : fg) + i*512;
  g_wcat[idx] = tf32rna(G[k] * W[(size_t)k*2048 + src]);
}

__global__ __launch_bounds__(128) void build_bcat(
  const float* __restrict__ fw, const float* __restrict__ bw,
  const float* __restrict__ fb, const float* __restrict__ bb,     // ln betas
  const float* __restrict__ fib, const float* __restrict__ bib)   // in biases
{
  int n = blockIdx.x;          // 0..4095
  int i = blockIdx.y;          // layer
  int br = n >> 11;
  int j2 = n & 2047;
  int src = (j2 & 1) ? 1024 + (j2 >> 1) : (j2 >> 1);
  const float* W   = (br ? bw : fw) + (size_t)i*512*2048;
  const float* LNB = (br ? bb : fb) + i*512;
  const float* INB = (br ? bib : fib) + i*2048;
  __shared__ float sh[4];
  float p = 0.f;
  for (int k = threadIdx.x; k < 512; k += 128)
    p += LNB[k] * W[(size_t)k*2048 + src];
  float tot = block_sum_128(p, sh);
  if (threadIdx.x == 0) g_bcat[i*4096 + n] = tot + INB[src];
}

__global__ __launch_bounds__(256) void build_wf1(
  const float* __restrict__ w1, const float* __restrict__ g)
{
  size_t idx = (size_t)blockIdx.x*256 + threadIdx.x;   // 2*512*2048
  int k = (int)((idx >> 11) & 511);
  int i = (int)(idx >> 20);
  g_wf1[idx] = tf32rna(g[i*512 + k] * w1[idx]);
}

__global__ __launch_bounds__(128) void build_bf1(
  const float* __restrict__ w1, const float* __restrict__ lnb,
  const float* __restrict__ b1)
{
  int n = blockIdx.x;          // 0..2047
  int i = blockIdx.y;
  const float* W = w1 + (size_t)i*512*2048;
  __shared__ float sh[4];
  float p = 0.f;
  for (int k = threadIdx.x; k < 512; k += 128)
    p += lnb[i*512 + k] * W[(size_t)k*2048 + n];
  float tot = block_sum_128(p, sh);
  if (threadIdx.x == 0) g_bf1[i*2048 + n] = tot + b1[i*2048 + n];
}

// Wmid rows 2048..2559 = Mt + Mb (tf32-rounded)
__global__ __launch_bounds__(256) void build_wmid_sum(const float* __restrict__ mw)
{
  size_t idx = (size_t)blockIdx.x*256 + threadIdx.x;   // 2*512*512
  int c = idx & 511;
  int k = (int)((idx >> 9) & 511);
  int i = (int)(idx >> 18);
  const float* Mt = mw + (size_t)i*1024*512;
  g_wmid[(size_t)i*2560*512 + (size_t)(2048 + k)*512 + c] =
      tf32rna(Mt[(size_t)k*512 + c] + Mt[(size_t)(512 + k)*512 + c]);
}

__global__ __launch_bounds__(128) void build_bmid(
  const float* __restrict__ mw, const float* __restrict__ mb,
  const float* __restrict__ fob, const float* __restrict__ bob)
{
  int c = blockIdx.x;          // 0..511
  int i = blockIdx.y;
  const float* Mt = mw + (size_t)i*1024*512;
  __shared__ float sh[4];
  float p = 0.f;
  for (int k = threadIdx.x; k < 512; k += 128){
    p += fob[i*512 + k] * Mt[(size_t)k*512 + c];
    p += bob[i*512 + k] * Mt[(size_t)(512 + k)*512 + c];
  }
  float tot = block_sum_128(p, sh);
  if (threadIdx.x == 0) g_bmid[i*512 + c] = tot + mb[i*512 + c];
}

// ---------------- host orchestration ----------------------------------------
extern "C" void kernel_launch(void* const* d_in, const int* in_sizes, int n_in,
                              void* d_out, int out_size)
{
  const float* slots     = (const float*)d_in[0];
  const float* keep      = (const float*)d_in[1];
  const float* attn      = (const float*)d_in[2];
  const float* pm1_w     = (const float*)d_in[5];
  const float* pm1_b     = (const float*)d_in[6];
  const float* pm2_w     = (const float*)d_in[7];
  const float* pm2_b     = (const float*)d_in[8];
  const float* fwd_ln_g  = (const float*)d_in[9];
  const float* fwd_ln_b  = (const float*)d_in[10];
  const float* fwd_in_w  = (const float*)d_in[11];
  const float* fwd_in_b  = (const float*)d_in[12];
  const float* fwd_out_w = (const float*)d_in[13];
  const float* fwd_out_b = (const float*)d_in[14];
  const float* bwd_ln_g  = (const float*)d_in[15];
  const float* bwd_ln_b  = (const float*)d_in[16];
  const float* bwd_in_w  = (const float*)d_in[17];
  const float* bwd_in_b  = (const float*)d_in[18];
  const float* bwd_out_w = (const float*)d_in[19];
  const float* bwd_out_b = (const float*)d_in[20];
  const float* merge_w   = (const float*)d_in[21];
  const float* merge_b   = (const float*)d_in[22];
  const float* norm_g    = (const float*)d_in[23];
  const float* norm_b    = (const float*)d_in[24];
  const float* ffn_ln_g  = (const float*)d_in[25];
  const float* ffn_ln_b  = (const float*)d_in[26];
  const float* ffn1_w    = (const float*)d_in[27];
  const float* ffn1_b    = (const float*)d_in[28];
  const float* ffn2_w    = (const float*)d_in[29];
  const float* ffn2_b    = (const float*)d_in[30];
  float* out = (float*)d_out;

  float *xg, *lnf, *hh, *res, *enc, *cent, *wcat, *bcat, *wmid, *bmid, *wf1, *bf1, *zb;
  cudaGetSymbolAddress((void**)&xg,   g_x);
  cudaGetSymbolAddress((void**)&lnf,  g_lnf);
  cudaGetSymbolAddress((void**)&hh,   g_h);
  cudaGetSymbolAddress((void**)&res,  g_res);
  cudaGetSymbolAddress((void**)&enc,  g_enc);
  cudaGetSymbolAddress((void**)&cent, g_cent);
  cudaGetSymbolAddress((void**)&wcat, g_wcat);
  cudaGetSymbolAddress((void**)&bcat, g_bcat);
  cudaGetSymbolAddress((void**)&wmid, g_wmid);
  cudaGetSymbolAddress((void**)&bmid, g_bmid);
  cudaGetSymbolAddress((void**)&wf1,  g_wf1);
  cudaGetSymbolAddress((void**)&bf1,  g_bf1);
  cudaGetSymbolAddress((void**)&zb,   g_zero);

  float* cent_out = nullptr;
  if ((long long)out_size >= (long long)Mz*Dz + (long long)Mz*2)
    cent_out = out + (size_t)Mz*Dz;

  cudaFuncSetAttribute(gemm2<0,false,false>, cudaFuncAttributeMaxDynamicSharedMemorySize, DSMEM_BYTES);
  cudaFuncSetAttribute(gemm2<1,false,false>, cudaFuncAttributeMaxDynamicSharedMemorySize, DSMEM_BYTES);
  cudaFuncSetAttribute(gemm2<0,true ,false>, cudaFuncAttributeMaxDynamicSharedMemorySize, DSMEM_BYTES);
  cudaFuncSetAttribute(gemm2<0,true ,true >, cudaFuncAttributeMaxDynamicSharedMemorySize, DSMEM_BYTES);
  cudaFuncSetAttribute(gemm2<2,false,false>, cudaFuncAttributeMaxDynamicSharedMemorySize, DSMEM_BYTES);

  const dim3 blk(128);

  // ---- precompute (runs every replay; tiny) ----
  build_wcat<<<16384, 256>>>(fwd_in_w, bwd_in_w, fwd_ln_g, bwd_ln_g);
  build_bcat<<<dim3(4096,2), 128>>>(fwd_in_w, bwd_in_w, fwd_ln_b, bwd_ln_b, fwd_in_b, bwd_in_b);
  build_wf1<<<8192, 256>>>(ffn1_w, ffn_ln_g);
  build_bf1<<<dim3(2048,2), 128>>>(ffn1_w, ffn_ln_b, ffn1_b);
  for (int i = 0; i < Lz; i++){
    // Wmid rows 0..1023 = fwd_out_w @ Mt ; rows 1024..2047 = bwd_out_w @ Mb
    gemm2<0,false,false><<<dim3(4,8), blk, DSMEM_BYTES>>>(
        fwd_out_w + (size_t)i*1024*512, 512, 512,
        fwd_out_w, 512, 512,
        merge_w + (size_t)i*1024*512, 512, zb,
        nullptr, 0, nullptr,
        wmid + (size_t)i*2560*512, 512);
    gemm2<0,false,false><<<dim3(4,8), blk, DSMEM_BYTES>>>(
        bwd_out_w + (size_t)i*1024*512, 512, 512,
        bwd_out_w, 512, 512,
        merge_w + (size_t)i*1024*512 + (size_t)512*512, 512, zb,
        nullptr, 0, nullptr,
        wmid + (size_t)i*2560*512 + (size_t)1024*512, 512);
  }
  build_wmid_sum<<<2048, 256>>>(merge_w);
  build_bmid<<<dim3(512,2), 128>>>(merge_w, merge_b, fwd_out_b, bwd_out_b);

  // ---- positional encoding path ----
  centroid_kernel<<<Mz, 256>>>(attn, cent, cent_out);
  enc_kernel<<<Mz, 256>>>(cent, enc);
  gemm2<1,false,false><<<dim3(4,128), blk, DSMEM_BYTES>>>(
      enc, 256, 256, enc, 256, 256, pm1_w, 512, pm1_b,
      nullptr, 0, nullptr, lnf, 512);
  gemm2<0,true,false><<<dim3(4,128), blk, DSMEM_BYTES>>>(
      lnf, 512, 512, lnf, 512, 512, pm2_w, 512, pm2_b,
      slots, 512, nullptr, xg, 512);

  // ---- layers ----
  for (int i = 0; i < Lz; i++){
    // n-hat of x
    ln_plain_kernel<<<Mz, 128>>>(xg, lnf);
    // fused fwd+bwd in-proj with GLU epilogue -> hh[:, 0..1023]=af, [1024..2047]=ab
    gemm2<2,false,false><<<dim3(32,128), blk, DSMEM_BYTES>>>(
        lnf, 512, 512, lnf, 512, 512,
        wcat + (size_t)i*512*4096, 4096, bcat + (size_t)i*4096,
        nullptr, 0, nullptr, hh, 2048);
    // fused out-proj + merge + residual: res = x + [af|ab|x] @ Wmid + bmid
    gemm2<0,true,false><<<dim3(4,128), blk, DSMEM_BYTES>>>(
        hh, 2048, 2048, xg, 512, 2560,
        wmid + (size_t)i*2560*512, 512, bmid + (size_t)i*512,
        xg, 512, nullptr, res, 512);
    // post-norm + ffn-input normalize
    ln_chain2_kernel<<<Mz, 128>>>(res, norm_g + i*Dz, norm_b + i*Dz, xg, lnf);
    // ffn1 (folded LN affine) with gelu
    gemm2<1,false,false><<<dim3(16,128), blk, DSMEM_BYTES>>>(
        lnf, 512, 512, lnf, 512, 512,
        wf1 + (size_t)i*512*2048, 2048, bf1 + (size_t)i*2048,
        nullptr, 0, nullptr, hh, 2048);
    // ffn2 + residual + mask
    float* dst = (i == Lz-1) ? out : xg;
    gemm2<0,true,true><<<dim3(4,128), blk, DSMEM_BYTES>>>(
        hh, 2048, 2048, hh, 2048, 2048,
        ffn2_w + (size_t)i*2048*512, 512, ffn2_b + (size_t)i*512,
        xg, 512, keep, dst, 512);
  }
}